// round 1
// baseline (speedup 1.0000x reference)
#include <cuda_runtime.h>
#include <cstdint>
#include <cstddef>

#define NN 50000
#define EMAX 800000

// ---------------- scratch (device globals; no allocation allowed) ----------------
__device__ float g_h1[(size_t)NN * 128];
__device__ float g_h2[(size_t)NN * 128];
__device__ float g_xh[(size_t)NN * 256];
__device__ float g_agg[(size_t)NN * 256];
__device__ float g_feat[(size_t)NN * 256];
__device__ float g_ssrc[NN * 4];
__device__ float g_sdst[NN * 4];
__device__ int   g_off[NN + 1];
__device__ int   g_deg[NN];
__device__ int   g_cur[NN];
__device__ int   g_adj[EMAX];

__device__ __forceinline__ float lrelu(float x) { return fmaxf(x, 0.2f * x); }
__device__ __forceinline__ float elu1(float x)  { return x > 0.f ? x : expm1f(x); }

// ---------------- CSR build ----------------
__global__ void deg_kernel(const int* __restrict__ dst, int E) {
    int i = blockIdx.x * blockDim.x + threadIdx.x;
    if (i < E) atomicAdd(&g_deg[dst[i]], 1);
}

__global__ void scan_kernel(int n) {
    __shared__ int s[1024];
    int tid = threadIdx.x;
    const int chunk = (n + 1023) / 1024;
    int begin = tid * chunk;
    int endi  = min(begin + chunk, n);
    int sum = 0;
    for (int i = begin; i < endi; i++) sum += g_deg[i];
    s[tid] = sum;
    __syncthreads();
    for (int off = 1; off < 1024; off <<= 1) {
        int v = (tid >= off) ? s[tid - off] : 0;
        __syncthreads();
        s[tid] += v;
        __syncthreads();
    }
    int run = (tid == 0) ? 0 : s[tid - 1];
    for (int i = begin; i < endi; i++) { g_off[i] = run; run += g_deg[i]; }
    if (tid == 1023) g_off[n] = s[1023];
}

__global__ void scatter_kernel(const int* __restrict__ src, const int* __restrict__ dst, int E) {
    int i = blockIdx.x * blockDim.x + threadIdx.x;
    if (i < E) {
        int d = dst[i];
        int pos = g_off[d] + atomicAdd(&g_cur[d], 1);
        g_adj[pos] = src[i];
    }
}

// ---------------- GEMM: C[M,Nc] = A[M,K] @ B[K,Nc] (+bias)(+relu) ----------------
// BM=128, BN=64, BK=16, 256 threads, 8x4 micro-tile. K%16==0, Nc%64==0 required.
__global__ __launch_bounds__(256) void gemm_kernel(
    const float* __restrict__ A, const float* __restrict__ B,
    const float* __restrict__ bias, float* __restrict__ C,
    int M, int K, int Nc, int act)
{
    __shared__ float As[16][129];
    __shared__ float Bs[16][65];
    int bm = blockIdx.y * 128;
    int bn = blockIdx.x * 64;
    int tid = threadIdx.x;
    int tx = tid & 15;
    int ty = tid >> 4;
    float acc[8][4];
#pragma unroll
    for (int i = 0; i < 8; i++)
#pragma unroll
        for (int j = 0; j < 4; j++) acc[i][j] = 0.f;

    for (int k0 = 0; k0 < K; k0 += 16) {
#pragma unroll
        for (int l = 0; l < 8; l++) {
            int i = tid + l * 256;
            int m = i >> 4, kk = i & 15;
            int gm = bm + m;
            As[kk][m] = (gm < M) ? A[(size_t)gm * K + k0 + kk] : 0.f;
        }
#pragma unroll
        for (int l = 0; l < 4; l++) {
            int i = tid + l * 256;
            int kk = i >> 6, n = i & 63;
            Bs[kk][n] = B[(size_t)(k0 + kk) * Nc + bn + n];
        }
        __syncthreads();
#pragma unroll
        for (int kk = 0; kk < 16; kk++) {
            float a[8], b[4];
#pragma unroll
            for (int i = 0; i < 8; i++) a[i] = As[kk][ty * 8 + i];
#pragma unroll
            for (int j = 0; j < 4; j++) b[j] = Bs[kk][tx * 4 + j];
#pragma unroll
            for (int i = 0; i < 8; i++)
#pragma unroll
                for (int j = 0; j < 4; j++)
                    acc[i][j] = fmaf(a[i], b[j], acc[i][j]);
        }
        __syncthreads();
    }
#pragma unroll
    for (int i = 0; i < 8; i++) {
        int gm = bm + ty * 8 + i;
        if (gm >= M) continue;
#pragma unroll
        for (int j = 0; j < 4; j++) {
            int gn = bn + tx * 4 + j;
            float v = acc[i][j];
            if (bias) v += bias[gn];
            if (act == 1) v = fmaxf(v, 0.f);
            C[(size_t)gm * Nc + gn] = v;
        }
    }
}

// ---------------- attention scores: s[n,h] = <xh[n,h,:], a[h,:]> ----------------
// one warp per (node, head); D = 64 fixed.
__global__ void score_kernel(const float* __restrict__ xh,
                             const float* __restrict__ asrc,
                             const float* __restrict__ adst,
                             float* __restrict__ ssrc, float* __restrict__ sdst, int H)
{
    int w = (blockIdx.x * blockDim.x + threadIdx.x) >> 5;
    int lane = threadIdx.x & 31;
    if (w >= NN * H) return;
    int n = w / H, h = w - n * H;
    int F = H * 64;
    const float* row = xh + (size_t)n * F + h * 64;
    float x0 = row[lane], x1 = row[lane + 32];
    float vs = x0 * asrc[h * 64 + lane] + x1 * asrc[h * 64 + lane + 32];
    float vd = x0 * adst[h * 64 + lane] + x1 * adst[h * 64 + lane + 32];
#pragma unroll
    for (int o = 16; o; o >>= 1) {
        vs += __shfl_xor_sync(0xffffffffu, vs, o);
        vd += __shfl_xor_sync(0xffffffffu, vd, o);
    }
    if (lane == 0) { ssrc[w] = vs; sdst[w] = vd; }
}

// ---------------- segment-softmax aggregation ----------------
// one warp per (node, head); lanes cover D=64 (d=lane, d=lane+32).
// 2-pass: max, then sum-of-exp fused with weighted gather; divide by z at end.
// Self-loop handled explicitly (reference appends one per node).
__global__ void agg_kernel(const float* __restrict__ xh,
                           const float* __restrict__ ssrc,
                           const float* __restrict__ sdst,
                           float* __restrict__ agg, int H)
{
    int w = (blockIdx.x * blockDim.x + threadIdx.x) >> 5;
    int lane = threadIdx.x & 31;
    if (w >= NN * H) return;
    int n = w / H, h = w - n * H;
    int F = H * 64;
    int start = g_off[n], end = g_off[n + 1];
    float sd = sdst[n * H + h];
    float eself = lrelu(ssrc[n * H + h] + sd);

    // pass 1: max over incoming edges + self-loop
    float m = eself;
    for (int j = start + lane; j < end; j += 32) {
        int s = g_adj[j];
        m = fmaxf(m, lrelu(ssrc[s * H + h] + sd));
    }
#pragma unroll
    for (int o = 16; o; o >>= 1) m = fmaxf(m, __shfl_xor_sync(0xffffffffu, m, o));

    // pass 2: z = sum exp, acc = sum w * xh[src]
    float wself = __expf(eself - m);
    float zpart = (lane == 0) ? wself : 0.f;
    const float* selfrow = xh + (size_t)n * F + h * 64;
    float acc0 = wself * selfrow[lane];
    float acc1 = wself * selfrow[lane + 32];

    for (int j0 = start; j0 < end; j0 += 32) {
        int j = j0 + lane;
        int s = (j < end) ? g_adj[j] : n;
        float wv = 0.f;
        if (j < end) {
            wv = __expf(lrelu(ssrc[s * H + h] + sd) - m);
            zpart += wv;
        }
        int cnt = min(32, end - j0);
        for (int k = 0; k < cnt; k++) {
            float wk = __shfl_sync(0xffffffffu, wv, k);
            int   sk = __shfl_sync(0xffffffffu, s, k);
            const float* r = xh + (size_t)sk * F + h * 64;
            acc0 = fmaf(wk, r[lane], acc0);
            acc1 = fmaf(wk, r[lane + 32], acc1);
        }
    }
#pragma unroll
    for (int o = 16; o; o >>= 1) zpart += __shfl_xor_sync(0xffffffffu, zpart, o);
    float inv = 1.f / zpart;
    agg[(size_t)n * F + h * 64 + lane]      = acc0 * inv;
    agg[(size_t)n * F + h * 64 + lane + 32] = acc1 * inv;
}

// ---------------- epilogues ----------------
__global__ void bias_elu_kernel(const float* __restrict__ in, const float* __restrict__ b,
                                float* __restrict__ out, int total, int Fmask) {
    int i = blockIdx.x * blockDim.x + threadIdx.x;
    if (i < total) out[i] = elu1(in[i] + b[i & Fmask]);
}

__global__ void mean2_bias_elu_kernel(const float* __restrict__ in, const float* __restrict__ b,
                                      float* __restrict__ out, int total) {
    int i = blockIdx.x * blockDim.x + threadIdx.x;
    if (i < total) {
        int n = i >> 6, d = i & 63;
        float v = 0.5f * (in[(size_t)n * 128 + d] + in[(size_t)n * 128 + 64 + d]) + b[d];
        out[i] = elu1(v);
    }
}

__global__ void final_bias_kernel(const float* __restrict__ in, const float* __restrict__ b,
                                  float* __restrict__ out, int total) {
    int i = blockIdx.x * blockDim.x + threadIdx.x;
    if (i < total) out[i] = in[i] + b[i & 63];
}

// ---------------- host ----------------
extern "C" void kernel_launch(void* const* d_in, const int* in_sizes, int n_in,
                              void* d_out, int out_size) {
    const float* x     = (const float*)d_in[0];
    const int*   ei    = (const int*)  d_in[1];   // [2, E] int32
    const float* w1    = (const float*)d_in[2];
    const float* b1    = (const float*)d_in[3];
    const float* w2    = (const float*)d_in[4];
    const float* b2    = (const float*)d_in[5];
    const float* g1w   = (const float*)d_in[6];
    const float* g1as  = (const float*)d_in[7];
    const float* g1ad  = (const float*)d_in[8];
    const float* g1b   = (const float*)d_in[9];
    const float* g2w   = (const float*)d_in[10];
    const float* g2as  = (const float*)d_in[11];
    const float* g2ad  = (const float*)d_in[12];
    const float* g2b   = (const float*)d_in[13];
    const float* g3w   = (const float*)d_in[14];
    const float* g3as  = (const float*)d_in[15];
    const float* g3ad  = (const float*)d_in[16];
    const float* g3b   = (const float*)d_in[17];

    int E = in_sizes[1] / 2;
    if (E > EMAX) E = EMAX;
    const int* srcp = ei;
    const int* dstp = ei + E;

    float *h1, *h2, *xh, *agg, *feat, *ssrc, *sdst;
    int *deg, *cur;
    cudaGetSymbolAddress((void**)&h1,   g_h1);
    cudaGetSymbolAddress((void**)&h2,   g_h2);
    cudaGetSymbolAddress((void**)&xh,   g_xh);
    cudaGetSymbolAddress((void**)&agg,  g_agg);
    cudaGetSymbolAddress((void**)&feat, g_feat);
    cudaGetSymbolAddress((void**)&ssrc, g_ssrc);
    cudaGetSymbolAddress((void**)&sdst, g_sdst);
    cudaGetSymbolAddress((void**)&deg,  g_deg);
    cudaGetSymbolAddress((void**)&cur,  g_cur);

    // ---- CSR build (per launch; deterministic) ----
    cudaMemsetAsync(deg, 0, NN * sizeof(int));
    cudaMemsetAsync(cur, 0, NN * sizeof(int));
    deg_kernel<<<(E + 255) / 256, 256>>>(dstp, E);
    scan_kernel<<<1, 1024>>>(NN);
    scatter_kernel<<<(E + 255) / 256, 256>>>(srcp, dstp, E);

    const int GY = (NN + 127) / 128;   // 391

    // ---- semantic MLP ----
    gemm_kernel<<<dim3(2, GY), 256>>>(x,  w1, b1, h1, NN, 256, 128, 1);
    gemm_kernel<<<dim3(2, GY), 256>>>(h1, w2, b2, h2, NN, 128, 128, 1);

    // ---- GAT 1: HID(128) -> 4 heads x 64, concat, elu ----
    gemm_kernel<<<dim3(4, GY), 256>>>(h2, g1w, nullptr, xh, NN, 128, 256, 0);
    {
        int W = NN * 4;
        score_kernel<<<(W * 32 + 255) / 256, 256>>>(xh, g1as, g1ad, ssrc, sdst, 4);
        agg_kernel  <<<(W * 32 + 255) / 256, 256>>>(xh, ssrc, sdst, agg, 4);
        int tot = NN * 256;
        bias_elu_kernel<<<(tot + 1023) / 1024, 1024>>>(agg, g1b, feat, tot, 255);
    }

    // ---- GAT 2: 256 -> 2 heads x 64, mean, elu ----
    gemm_kernel<<<dim3(2, GY), 256>>>(feat, g2w, nullptr, xh, NN, 256, 128, 0);
    {
        int W = NN * 2;
        score_kernel<<<(W * 32 + 255) / 256, 256>>>(xh, g2as, g2ad, ssrc, sdst, 2);
        agg_kernel  <<<(W * 32 + 255) / 256, 256>>>(xh, ssrc, sdst, agg, 2);
        int tot = NN * 64;
        mean2_bias_elu_kernel<<<(tot + 1023) / 1024, 1024>>>(agg, g2b, h1, tot);
    }

    // ---- GAT 3: 64 -> 1 head x 64, mean(=identity), no activation ----
    gemm_kernel<<<dim3(1, GY), 256>>>(h1, g3w, nullptr, xh, NN, 64, 64, 0);
    {
        int W = NN;
        score_kernel<<<(W * 32 + 255) / 256, 256>>>(xh, g3as, g3ad, ssrc, sdst, 1);
        agg_kernel  <<<(W * 32 + 255) / 256, 256>>>(xh, ssrc, sdst, agg, 1);
        int tot = NN * 64;
        final_bias_kernel<<<(tot + 1023) / 1024, 1024>>>(agg, g3b, (float*)d_out, tot);
    }
}

// round 3
// speedup vs baseline: 1.0017x; 1.0017x over previous
#include <cuda_runtime.h>
#include <cstdint>
#include <cstddef>

#define NN 50000
#define EMAX 800000

// ---------------- scratch (device globals; no allocation allowed) ----------------
__device__ float g_h1[(size_t)NN * 128];
__device__ float g_h2[(size_t)NN * 128];
__device__ float g_xh[(size_t)NN * 256];
__device__ float g_agg[(size_t)NN * 256];
__device__ float g_feat[(size_t)NN * 256];
__device__ float g_ssrc[NN * 4];
__device__ float g_sdst[NN * 4];
__device__ int   g_off[NN + 1];
__device__ int   g_deg[NN];
__device__ int   g_cur[NN];
__device__ int   g_adj[EMAX];

__device__ __forceinline__ float lrelu(float x) { return fmaxf(x, 0.2f * x); }
__device__ __forceinline__ float elu1(float x)  { return x > 0.f ? x : expm1f(x); }

// ---------------- CSR build ----------------
__global__ void deg_kernel(const int* __restrict__ dst, int E) {
    int i = blockIdx.x * blockDim.x + threadIdx.x;
    if (i < E) atomicAdd(&g_deg[dst[i]], 1);
}

__global__ void scan_kernel(int n) {
    __shared__ int s[1024];
    int tid = threadIdx.x;
    const int chunk = (n + 1023) / 1024;
    int begin = tid * chunk;
    int endi  = min(begin + chunk, n);
    int sum = 0;
    for (int i = begin; i < endi; i++) sum += g_deg[i];
    s[tid] = sum;
    __syncthreads();
    for (int off = 1; off < 1024; off <<= 1) {
        int v = (tid >= off) ? s[tid - off] : 0;
        __syncthreads();
        s[tid] += v;
        __syncthreads();
    }
    int run = (tid == 0) ? 0 : s[tid - 1];
    for (int i = begin; i < endi; i++) { g_off[i] = run; run += g_deg[i]; }
    if (tid == 1023) g_off[n] = s[1023];
}

__global__ void scatter_kernel(const int* __restrict__ src, const int* __restrict__ dst, int E) {
    int i = blockIdx.x * blockDim.x + threadIdx.x;
    if (i < E) {
        int d = dst[i];
        int pos = g_off[d] + atomicAdd(&g_cur[d], 1);
        g_adj[pos] = src[i];
    }
}

// ---------------- SGEMM: C[M,Nc] = A[M,K] @ B[K,Nc] (+bias)(+relu) ----------------
// BM=128, BN=128, BK=8, 256 threads, 8x8 micro-tile, float4 everywhere,
// register-prefetch double-buffered smem, 1 sync per K-stage.
// Requires K%8==0, Nc%4==0.
__global__ __launch_bounds__(256, 2) void sgemm_kernel(
    const float* __restrict__ A, const float* __restrict__ B,
    const float* __restrict__ bias, float* __restrict__ C,
    int M, int K, int Nc, int act)
{
    __shared__ float As[2][8][128];
    __shared__ float Bs[2][8][128];

    const int tid = threadIdx.x;
    const int bm = blockIdx.y * 128;
    const int bn = blockIdx.x * 128;

    const int arow = tid >> 1;            // 0..127
    const int acol = (tid & 1) << 2;      // 0 or 4
    const int brow = tid >> 5;            // 0..7
    const int bcol = (tid & 31) << 2;     // 0..124

    const int tx = tid & 15;              // col group
    const int ty = tid >> 4;              // row group

    const bool aval = (bm + arow) < M;
    const bool bval = (bn + bcol) < Nc;
    const float* Aptr = A + (size_t)(bm + arow) * K + acol;
    const float* Bptr = B + (size_t)brow * Nc + (bn + bcol);

    float4 ar = make_float4(0.f, 0.f, 0.f, 0.f);
    float4 br = make_float4(0.f, 0.f, 0.f, 0.f);
    if (aval) ar = *(const float4*)Aptr;
    if (bval) br = *(const float4*)Bptr;

    As[0][acol + 0][arow] = ar.x;
    As[0][acol + 1][arow] = ar.y;
    As[0][acol + 2][arow] = ar.z;
    As[0][acol + 3][arow] = ar.w;
    *(float4*)&Bs[0][brow][bcol] = br;
    __syncthreads();

    float acc[8][8];
#pragma unroll
    for (int i = 0; i < 8; i++)
#pragma unroll
        for (int j = 0; j < 8; j++) acc[i][j] = 0.f;

    int buf = 0;
    for (int k0 = 0; k0 < K; k0 += 8) {
        const bool has_next = (k0 + 8) < K;
        if (has_next) {
            ar = make_float4(0.f, 0.f, 0.f, 0.f);
            br = make_float4(0.f, 0.f, 0.f, 0.f);
            if (aval) ar = *(const float4*)(Aptr + (k0 + 8));
            if (bval) br = *(const float4*)(Bptr + (size_t)(k0 + 8) * Nc);
        }
#pragma unroll
        for (int kk = 0; kk < 8; kk++) {
            float4 a0 = *(const float4*)&As[buf][kk][ty * 8];
            float4 a1 = *(const float4*)&As[buf][kk][ty * 8 + 4];
            float4 b0 = *(const float4*)&Bs[buf][kk][tx * 8];
            float4 b1 = *(const float4*)&Bs[buf][kk][tx * 8 + 4];
            float a[8] = {a0.x, a0.y, a0.z, a0.w, a1.x, a1.y, a1.z, a1.w};
            float b[8] = {b0.x, b0.y, b0.z, b0.w, b1.x, b1.y, b1.z, b1.w};
#pragma unroll
            for (int i = 0; i < 8; i++)
#pragma unroll
                for (int j = 0; j < 8; j++)
                    acc[i][j] = fmaf(a[i], b[j], acc[i][j]);
        }
        if (has_next) {
            buf ^= 1;
            As[buf][acol + 0][arow] = ar.x;
            As[buf][acol + 1][arow] = ar.y;
            As[buf][acol + 2][arow] = ar.z;
            As[buf][acol + 3][arow] = ar.w;
            *(float4*)&Bs[buf][brow][bcol] = br;
            __syncthreads();
        }
    }

    // epilogue: vectorized stores
#pragma unroll
    for (int i = 0; i < 8; i++) {
        int gm = bm + ty * 8 + i;
        if (gm >= M) continue;
#pragma unroll
        for (int jv = 0; jv < 2; jv++) {
            int gn = bn + tx * 8 + jv * 4;
            if (gn + 3 >= Nc) {
                for (int j = 0; j < 4; j++) {
                    int g = gn + j;
                    if (g < Nc) {
                        float v = acc[i][jv * 4 + j];
                        if (bias) v += bias[g];
                        if (act == 1) v = fmaxf(v, 0.f);
                        C[(size_t)gm * Nc + g] = v;
                    }
                }
            } else {
                float4 v;
                v.x = acc[i][jv * 4 + 0];
                v.y = acc[i][jv * 4 + 1];
                v.z = acc[i][jv * 4 + 2];
                v.w = acc[i][jv * 4 + 3];
                if (bias) {
                    v.x += bias[gn + 0]; v.y += bias[gn + 1];
                    v.z += bias[gn + 2]; v.w += bias[gn + 3];
                }
                if (act == 1) {
                    v.x = fmaxf(v.x, 0.f); v.y = fmaxf(v.y, 0.f);
                    v.z = fmaxf(v.z, 0.f); v.w = fmaxf(v.w, 0.f);
                }
                *(float4*)&C[(size_t)gm * Nc + gn] = v;
            }
        }
    }
}

// ---------------- attention scores: s[n,h] = <xh[n,h,:], a[h,:]> ----------------
__global__ void score_kernel(const float* __restrict__ xh,
                             const float* __restrict__ asrc,
                             const float* __restrict__ adst,
                             float* __restrict__ ssrc, float* __restrict__ sdst, int H)
{
    int w = (blockIdx.x * blockDim.x + threadIdx.x) >> 5;
    int lane = threadIdx.x & 31;
    if (w >= NN * H) return;
    int n = w / H, h = w - n * H;
    int F = H * 64;
    const float* row = xh + (size_t)n * F + h * 64;
    float x0 = row[lane], x1 = row[lane + 32];
    float vs = x0 * asrc[h * 64 + lane] + x1 * asrc[h * 64 + lane + 32];
    float vd = x0 * adst[h * 64 + lane] + x1 * adst[h * 64 + lane + 32];
#pragma unroll
    for (int o = 16; o; o >>= 1) {
        vs += __shfl_xor_sync(0xffffffffu, vs, o);
        vd += __shfl_xor_sync(0xffffffffu, vd, o);
    }
    if (lane == 0) { ssrc[w] = vs; sdst[w] = vd; }
}

// ---------------- segment-softmax aggregation ----------------
__global__ void agg_kernel(const float* __restrict__ xh,
                           const float* __restrict__ ssrc,
                           const float* __restrict__ sdst,
                           float* __restrict__ agg, int H)
{
    int w = (blockIdx.x * blockDim.x + threadIdx.x) >> 5;
    int lane = threadIdx.x & 31;
    if (w >= NN * H) return;
    int n = w / H, h = w - n * H;
    int F = H * 64;
    int start = g_off[n], end = g_off[n + 1];
    float sd = sdst[n * H + h];
    float eself = lrelu(ssrc[n * H + h] + sd);

    // pass 1: max over incoming edges + self-loop
    float m = eself;
    for (int j = start + lane; j < end; j += 32) {
        int s = g_adj[j];
        m = fmaxf(m, lrelu(ssrc[s * H + h] + sd));
    }
#pragma unroll
    for (int o = 16; o; o >>= 1) m = fmaxf(m, __shfl_xor_sync(0xffffffffu, m, o));

    // pass 2: z = sum exp, acc = sum w * xh[src]
    float wself = __expf(eself - m);
    float zpart = (lane == 0) ? wself : 0.f;
    const float* selfrow = xh + (size_t)n * F + h * 64;
    float acc0 = wself * selfrow[lane];
    float acc1 = wself * selfrow[lane + 32];

    for (int j0 = start; j0 < end; j0 += 32) {
        int j = j0 + lane;
        int s = (j < end) ? g_adj[j] : n;
        float wv = 0.f;
        if (j < end) {
            wv = __expf(lrelu(ssrc[s * H + h] + sd) - m);
            zpart += wv;
        }
        int cnt = min(32, end - j0);
        for (int k = 0; k < cnt; k++) {
            float wk = __shfl_sync(0xffffffffu, wv, k);
            int   sk = __shfl_sync(0xffffffffu, s, k);
            const float* r = xh + (size_t)sk * F + h * 64;
            acc0 = fmaf(wk, r[lane], acc0);
            acc1 = fmaf(wk, r[lane + 32], acc1);
        }
    }
#pragma unroll
    for (int o = 16; o; o >>= 1) zpart += __shfl_xor_sync(0xffffffffu, zpart, o);
    float inv = 1.f / zpart;
    agg[(size_t)n * F + h * 64 + lane]      = acc0 * inv;
    agg[(size_t)n * F + h * 64 + lane + 32] = acc1 * inv;
}

// ---------------- epilogues ----------------
__global__ void bias_elu_kernel(const float* __restrict__ in, const float* __restrict__ b,
                                float* __restrict__ out, int total, int Fmask) {
    int i = blockIdx.x * blockDim.x + threadIdx.x;
    if (i < total) out[i] = elu1(in[i] + b[i & Fmask]);
}

__global__ void mean2_bias_elu_kernel(const float* __restrict__ in, const float* __restrict__ b,
                                      float* __restrict__ out, int total) {
    int i = blockIdx.x * blockDim.x + threadIdx.x;
    if (i < total) {
        int n = i >> 6, d = i & 63;
        float v = 0.5f * (in[(size_t)n * 128 + d] + in[(size_t)n * 128 + 64 + d]) + b[d];
        out[i] = elu1(v);
    }
}

__global__ void final_bias_kernel(const float* __restrict__ in, const float* __restrict__ b,
                                  float* __restrict__ out, int total) {
    int i = blockIdx.x * blockDim.x + threadIdx.x;
    if (i < total) out[i] = in[i] + b[i & 63];
}

// ---------------- host ----------------
extern "C" void kernel_launch(void* const* d_in, const int* in_sizes, int n_in,
                              void* d_out, int out_size) {
    const float* x     = (const float*)d_in[0];
    const int*   ei    = (const int*)  d_in[1];   // [2, E] int32
    const float* w1    = (const float*)d_in[2];
    const float* b1    = (const float*)d_in[3];
    const float* w2    = (const float*)d_in[4];
    const float* b2    = (const float*)d_in[5];
    const float* g1w   = (const float*)d_in[6];
    const float* g1as  = (const float*)d_in[7];
    const float* g1ad  = (const float*)d_in[8];
    const float* g1b   = (const float*)d_in[9];
    const float* g2w   = (const float*)d_in[10];
    const float* g2as  = (const float*)d_in[11];
    const float* g2ad  = (const float*)d_in[12];
    const float* g2b   = (const float*)d_in[13];
    const float* g3w   = (const float*)d_in[14];
    const float* g3as  = (const float*)d_in[15];
    const float* g3ad  = (const float*)d_in[16];
    const float* g3b   = (const float*)d_in[17];

    int E = in_sizes[1] / 2;
    if (E > EMAX) E = EMAX;
    const int* srcp = ei;
    const int* dstp = ei + E;

    float *h1, *h2, *xh, *agg, *feat, *ssrc, *sdst;
    int *deg, *cur;
    cudaGetSymbolAddress((void**)&h1,   g_h1);
    cudaGetSymbolAddress((void**)&h2,   g_h2);
    cudaGetSymbolAddress((void**)&xh,   g_xh);
    cudaGetSymbolAddress((void**)&agg,  g_agg);
    cudaGetSymbolAddress((void**)&feat, g_feat);
    cudaGetSymbolAddress((void**)&ssrc, g_ssrc);
    cudaGetSymbolAddress((void**)&sdst, g_sdst);
    cudaGetSymbolAddress((void**)&deg,  g_deg);
    cudaGetSymbolAddress((void**)&cur,  g_cur);

    // ---- CSR build (per launch; deterministic) ----
    cudaMemsetAsync(deg, 0, NN * sizeof(int));
    cudaMemsetAsync(cur, 0, NN * sizeof(int));
    deg_kernel<<<(E + 255) / 256, 256>>>(dstp, E);
    scan_kernel<<<1, 1024>>>(NN);
    scatter_kernel<<<(E + 255) / 256, 256>>>(srcp, dstp, E);

    const int GY = (NN + 127) / 128;   // 391

    // ---- semantic MLP ----
    sgemm_kernel<<<dim3(1, GY), 256>>>(x,  w1, b1, h1, NN, 256, 128, 1);
    sgemm_kernel<<<dim3(1, GY), 256>>>(h1, w2, b2, h2, NN, 128, 128, 1);

    // ---- GAT 1: HID(128) -> 4 heads x 64, concat, elu ----
    sgemm_kernel<<<dim3(2, GY), 256>>>(h2, g1w, nullptr, xh, NN, 128, 256, 0);
    {
        int W = NN * 4;
        score_kernel<<<(W * 32 + 255) / 256, 256>>>(xh, g1as, g1ad, ssrc, sdst, 4);
        agg_kernel  <<<(W * 32 + 255) / 256, 256>>>(xh, ssrc, sdst, agg, 4);
        int tot = NN * 256;
        bias_elu_kernel<<<(tot + 1023) / 1024, 1024>>>(agg, g1b, feat, tot, 255);
    }

    // ---- GAT 2: 256 -> 2 heads x 64, mean, elu ----
    sgemm_kernel<<<dim3(1, GY), 256>>>(feat, g2w, nullptr, xh, NN, 256, 128, 0);
    {
        int W = NN * 2;
        score_kernel<<<(W * 32 + 255) / 256, 256>>>(xh, g2as, g2ad, ssrc, sdst, 2);
        agg_kernel  <<<(W * 32 + 255) / 256, 256>>>(xh, ssrc, sdst, agg, 2);
        int tot = NN * 64;
        mean2_bias_elu_kernel<<<(tot + 1023) / 1024, 1024>>>(agg, g2b, h1, tot);
    }

    // ---- GAT 3: 64 -> 1 head x 64, mean(=identity), no activation ----
    sgemm_kernel<<<dim3(1, GY), 256>>>(h1, g3w, nullptr, xh, NN, 64, 64, 0);
    {
        int W = NN;
        score_kernel<<<(W * 32 + 255) / 256, 256>>>(xh, g3as, g3ad, ssrc, sdst, 1);
        agg_kernel  <<<(W * 32 + 255) / 256, 256>>>(xh, ssrc, sdst, agg, 1);
        int tot = NN * 64;
        final_bias_kernel<<<(tot + 1023) / 1024, 1024>>>(agg, g3b, (float*)d_out, tot);
    }
}

// round 5
// speedup vs baseline: 1.2433x; 1.2412x over previous
#include <cuda_runtime.h>
#include <cuda_bf16.h>
#include <cstdint>
#include <cstddef>

#define NN 50000
#define EMAX 800000

// ---------------- scratch (device globals; no allocation allowed) ----------------
__device__ float g_xh[(size_t)NN * 256];
__device__ float g_agg[(size_t)NN * 256];
__device__ float g_ssrc[NN * 4];
__device__ float g_sdst[NN * 4];
__device__ int   g_off[NN + 1];
__device__ int   g_deg[NN];
__device__ int   g_cur[NN];
__device__ int   g_adj[EMAX];

// split bf16 ping-pong activation buffers
__device__ __align__(16) __nv_bfloat16 g_Phi[(size_t)NN * 256];
__device__ __align__(16) __nv_bfloat16 g_Plo[(size_t)NN * 256];
__device__ __align__(16) __nv_bfloat16 g_Qhi[(size_t)NN * 256];
__device__ __align__(16) __nv_bfloat16 g_Qlo[(size_t)NN * 256];
__device__ __align__(16) __nv_bfloat16 g_whi[256 * 256];
__device__ __align__(16) __nv_bfloat16 g_wlo[256 * 256];

__device__ __forceinline__ float lrelu(float x) { return fmaxf(x, 0.2f * x); }
__device__ __forceinline__ float elu1(float x)  { return x > 0.f ? x : expm1f(x); }

// ---------------- CSR build ----------------
__global__ void deg_kernel(const int* __restrict__ dst, int E) {
    int i = blockIdx.x * blockDim.x + threadIdx.x;
    if (i < E) atomicAdd(&g_deg[dst[i]], 1);
}

__global__ void scan_kernel(int n) {
    __shared__ int s[1024];
    int tid = threadIdx.x;
    const int chunk = (n + 1023) / 1024;
    int begin = tid * chunk;
    int endi  = min(begin + chunk, n);
    int sum = 0;
    for (int i = begin; i < endi; i++) sum += g_deg[i];
    s[tid] = sum;
    __syncthreads();
    for (int off = 1; off < 1024; off <<= 1) {
        int v = (tid >= off) ? s[tid - off] : 0;
        __syncthreads();
        s[tid] += v;
        __syncthreads();
    }
    int run = (tid == 0) ? 0 : s[tid - 1];
    for (int i = begin; i < endi; i++) { g_off[i] = run; run += g_deg[i]; }
    if (tid == 1023) g_off[n] = s[1023];
}

__global__ void scatter_kernel(const int* __restrict__ src, const int* __restrict__ dst, int E) {
    int i = blockIdx.x * blockDim.x + threadIdx.x;
    if (i < E) {
        int d = dst[i];
        int pos = g_off[d] + atomicAdd(&g_cur[d], 1);
        g_adj[pos] = src[i];
    }
}

// ---------------- fp32 -> bf16 hi/lo split ----------------
__global__ void split_kernel(const float* __restrict__ a,
                             __nv_bfloat16* __restrict__ hi,
                             __nv_bfloat16* __restrict__ lo, int n) {
    int i = blockIdx.x * blockDim.x + threadIdx.x;
    if (i < n) {
        float f = a[i];
        __nv_bfloat16 h = __float2bfloat16(f);
        hi[i] = h;
        lo[i] = __float2bfloat16(f - __bfloat162float(h));
    }
}

// ---------------- tensor-core GEMM with split-bf16 operands ----------------
// Computes C[M,Nc] = A@B in fp32-equivalent precision via K' = 3K:
//   k' in [0,K): A_hi x B_hi;  [K,2K): A_lo x B_hi;  [2K,3K): A_hi x B_lo
// Block 128x128, BK=32, 256 thr (8 warps, warp tile 32x64), mma.m16n8k16.
// Output: fp32 (Cf) OR split bf16 (c_hi/c_lo). Optional bias + relu.
// Requires K%32==0, Nc%8==0.

__device__ __forceinline__ uint32_t sptr(const void* p) {
    return (uint32_t)__cvta_generic_to_shared(p);
}
__device__ __forceinline__ void ldsm4(uint32_t* r, uint32_t a) {
    asm volatile("ldmatrix.sync.aligned.m8n8.x4.shared.b16 {%0,%1,%2,%3},[%4];\n"
                 : "=r"(r[0]), "=r"(r[1]), "=r"(r[2]), "=r"(r[3]) : "r"(a));
}
__device__ __forceinline__ void ldsm4t(uint32_t* r, uint32_t a) {
    asm volatile("ldmatrix.sync.aligned.m8n8.x4.trans.shared.b16 {%0,%1,%2,%3},[%4];\n"
                 : "=r"(r[0]), "=r"(r[1]), "=r"(r[2]), "=r"(r[3]) : "r"(a));
}
__device__ __forceinline__ void mma16816(float* d, const uint32_t* a, uint32_t b0, uint32_t b1) {
    asm volatile("mma.sync.aligned.m16n8k16.row.col.f32.bf16.bf16.f32 "
                 "{%0,%1,%2,%3},{%4,%5,%6,%7},{%8,%9},{%0,%1,%2,%3};\n"
                 : "+f"(d[0]), "+f"(d[1]), "+f"(d[2]), "+f"(d[3])
                 : "r"(a[0]), "r"(a[1]), "r"(a[2]), "r"(a[3]), "r"(b0), "r"(b1));
}

#define A_PAD 40   // 32 + 8 bf16 pad -> 80B rows (conflict-free ldmatrix)
#define B_PAD 136  // 128 + 8 bf16 pad -> 272B rows

__global__ __launch_bounds__(256, 2) void tgemm_kernel(
    const __nv_bfloat16* __restrict__ a_hi, const __nv_bfloat16* __restrict__ a_lo,
    const __nv_bfloat16* __restrict__ b_hi, const __nv_bfloat16* __restrict__ b_lo,
    const float* __restrict__ bias,
    float* __restrict__ Cf,
    __nv_bfloat16* __restrict__ c_hi, __nv_bfloat16* __restrict__ c_lo,
    int M, int K, int Nc, int act)
{
    __shared__ __align__(16) __nv_bfloat16 As[2][128 * A_PAD];
    __shared__ __align__(16) __nv_bfloat16 Bs[2][32 * B_PAD];

    const int tid  = threadIdx.x;
    const int wid  = tid >> 5;
    const int lane = tid & 31;
    const int warp_m = (wid & 3) * 32;
    const int warp_n = (wid >> 2) * 64;
    const int bm = blockIdx.y * 128;
    const int bn = blockIdx.x * 128;

    const int id0_row = tid >> 2,          id0_c = tid & 3;
    const int id1_row = (tid + 256) >> 2,  id1_c = tid & 3;
    const int jd0_k   = tid >> 4,          jd0_c = tid & 15;
    const int jd1_k   = (tid + 256) >> 4,  jd1_c = tid & 15;

    const int nst = (3 * K) >> 5;

    // ---- stage 0 direct load ----
    {
        const __nv_bfloat16* Ab = a_hi;
        const __nv_bfloat16* Bb = b_hi;
        uint4 z = make_uint4(0, 0, 0, 0);
        uint4 v;
        int gm = bm + id0_row;
        v = (gm < M) ? *(const uint4*)(Ab + (size_t)gm * K + id0_c * 8) : z;
        *(uint4*)(&As[0][id0_row * A_PAD + id0_c * 8]) = v;
        gm = bm + id1_row;
        v = (gm < M) ? *(const uint4*)(Ab + (size_t)gm * K + id1_c * 8) : z;
        *(uint4*)(&As[0][id1_row * A_PAD + id1_c * 8]) = v;
        int gn = bn + jd0_c * 8;
        v = (gn < Nc) ? *(const uint4*)(Bb + (size_t)jd0_k * Nc + gn) : z;
        *(uint4*)(&Bs[0][jd0_k * B_PAD + jd0_c * 8]) = v;
        gn = bn + jd1_c * 8;
        v = (gn < Nc) ? *(const uint4*)(Bb + (size_t)jd1_k * Nc + gn) : z;
        *(uint4*)(&Bs[0][jd1_k * B_PAD + jd1_c * 8]) = v;
    }
    __syncthreads();

    float acc[2][8][4];
#pragma unroll
    for (int mt = 0; mt < 2; mt++)
#pragma unroll
        for (int n8 = 0; n8 < 8; n8++)
#pragma unroll
            for (int r = 0; r < 4; r++) acc[mt][n8][r] = 0.f;

    int buf = 0;
    for (int s = 0; s < nst; s++) {
        const bool pf = (s + 1) < nst;
        uint4 av0, av1, bv0, bv1;
        if (pf) {
            int k0 = (s + 1) * 32;
            int rg = k0 / K;
            int kk = k0 - rg * K;
            const __nv_bfloat16* Ab = (rg == 1) ? a_lo : a_hi;
            const __nv_bfloat16* Bb = (rg == 2) ? b_lo : b_hi;
            uint4 z = make_uint4(0, 0, 0, 0);
            int gm = bm + id0_row;
            av0 = (gm < M) ? *(const uint4*)(Ab + (size_t)gm * K + kk + id0_c * 8) : z;
            gm = bm + id1_row;
            av1 = (gm < M) ? *(const uint4*)(Ab + (size_t)gm * K + kk + id1_c * 8) : z;
            int gn = bn + jd0_c * 8;
            bv0 = (gn < Nc) ? *(const uint4*)(Bb + (size_t)(kk + jd0_k) * Nc + gn) : z;
            gn = bn + jd1_c * 8;
            bv1 = (gn < Nc) ? *(const uint4*)(Bb + (size_t)(kk + jd1_k) * Nc + gn) : z;
        }

        const uint32_t abase = sptr(&As[buf][0]);
        const uint32_t bbase = sptr(&Bs[buf][0]);
#pragma unroll
        for (int h = 0; h < 2; h++) {
            uint32_t afr0[4], afr1[4];
            int arow = warp_m + (lane & 15);
            uint32_t ad0 = abase + (uint32_t)(arow * (A_PAD * 2) + h * 32 + (lane >> 4) * 16);
            uint32_t ad1 = ad0 + 16 * (A_PAD * 2);
            ldsm4(afr0, ad0);
            ldsm4(afr1, ad1);
#pragma unroll
            for (int nt = 0; nt < 4; nt++) {
                uint32_t bfr[4];
                uint32_t bd = bbase
                    + (uint32_t)((h * 16 + (lane & 15)) * (B_PAD * 2)
                    + (warp_n + nt * 16 + ((lane >> 4) << 3)) * 2);
                ldsm4t(bfr, bd);
                mma16816(acc[0][nt * 2],     afr0, bfr[0], bfr[1]);
                mma16816(acc[0][nt * 2 + 1], afr0, bfr[2], bfr[3]);
                mma16816(acc[1][nt * 2],     afr1, bfr[0], bfr[1]);
                mma16816(acc[1][nt * 2 + 1], afr1, bfr[2], bfr[3]);
            }
        }

        if (pf) {
            int nb = buf ^ 1;
            *(uint4*)(&As[nb][id0_row * A_PAD + id0_c * 8]) = av0;
            *(uint4*)(&As[nb][id1_row * A_PAD + id1_c * 8]) = av1;
            *(uint4*)(&Bs[nb][jd0_k * B_PAD + jd0_c * 8]) = bv0;
            *(uint4*)(&Bs[nb][jd1_k * B_PAD + jd1_c * 8]) = bv1;
        }
        __syncthreads();
        buf ^= 1;
    }

    // ---- epilogue ----
#pragma unroll
    for (int mt = 0; mt < 2; mt++) {
#pragma unroll
        for (int n8 = 0; n8 < 8; n8++) {
            int col = bn + warp_n + n8 * 8 + (lane & 3) * 2;
            if (col >= Nc) continue;
            float bb0 = 0.f, bb1 = 0.f;
            if (bias) { bb0 = bias[col]; bb1 = bias[col + 1]; }
            int row0 = bm + warp_m + mt * 16 + (lane >> 2);
            float v0 = acc[mt][n8][0] + bb0;
            float v1 = acc[mt][n8][1] + bb1;
            float v2 = acc[mt][n8][2] + bb0;
            float v3 = acc[mt][n8][3] + bb1;
            if (act) {
                v0 = fmaxf(v0, 0.f); v1 = fmaxf(v1, 0.f);
                v2 = fmaxf(v2, 0.f); v3 = fmaxf(v3, 0.f);
            }
            if (row0 < M) {
                size_t o = (size_t)row0 * Nc + col;
                if (Cf) {
                    float2 p; p.x = v0; p.y = v1;
                    *(float2*)&Cf[o] = p;
                } else {
                    __nv_bfloat16 h0 = __float2bfloat16(v0);
                    __nv_bfloat16 h1 = __float2bfloat16(v1);
                    __nv_bfloat162 hp; hp.x = h0; hp.y = h1;
                    *(__nv_bfloat162*)&c_hi[o] = hp;
                    __nv_bfloat162 lp;
                    lp.x = __float2bfloat16(v0 - __bfloat162float(h0));
                    lp.y = __float2bfloat16(v1 - __bfloat162float(h1));
                    *(__nv_bfloat162*)&c_lo[o] = lp;
                }
            }
            int row1 = row0 + 8;
            if (row1 < M) {
                size_t o = (size_t)row1 * Nc + col;
                if (Cf) {
                    float2 p; p.x = v2; p.y = v3;
                    *(float2*)&Cf[o] = p;
                } else {
                    __nv_bfloat16 h0 = __float2bfloat16(v2);
                    __nv_bfloat16 h1 = __float2bfloat16(v3);
                    __nv_bfloat162 hp; hp.x = h0; hp.y = h1;
                    *(__nv_bfloat162*)&c_hi[o] = hp;
                    __nv_bfloat162 lp;
                    lp.x = __float2bfloat16(v2 - __bfloat162float(h0));
                    lp.y = __float2bfloat16(v3 - __bfloat162float(h1));
                    *(__nv_bfloat162*)&c_lo[o] = lp;
                }
            }
        }
    }
}

// ---------------- attention scores ----------------
__global__ void score_kernel(const float* __restrict__ xh,
                             const float* __restrict__ asrc,
                             const float* __restrict__ adst,
                             float* __restrict__ ssrc, float* __restrict__ sdst, int H)
{
    int w = (blockIdx.x * blockDim.x + threadIdx.x) >> 5;
    int lane = threadIdx.x & 31;
    if (w >= NN * H) return;
    int n = w / H, h = w - n * H;
    int F = H * 64;
    const float* row = xh + (size_t)n * F + h * 64;
    float x0 = row[lane], x1 = row[lane + 32];
    float vs = x0 * asrc[h * 64 + lane] + x1 * asrc[h * 64 + lane + 32];
    float vd = x0 * adst[h * 64 + lane] + x1 * adst[h * 64 + lane + 32];
#pragma unroll
    for (int o = 16; o; o >>= 1) {
        vs += __shfl_xor_sync(0xffffffffu, vs, o);
        vd += __shfl_xor_sync(0xffffffffu, vd, o);
    }
    if (lane == 0) { ssrc[w] = vs; sdst[w] = vd; }
}

// ---------------- segment-softmax aggregation ----------------
__global__ void agg_kernel(const float* __restrict__ xh,
                           const float* __restrict__ ssrc,
                           const float* __restrict__ sdst,
                           float* __restrict__ agg, int H)
{
    int w = (blockIdx.x * blockDim.x + threadIdx.x) >> 5;
    int lane = threadIdx.x & 31;
    if (w >= NN * H) return;
    int n = w / H, h = w - n * H;
    int F = H * 64;
    int start = g_off[n], end = g_off[n + 1];
    float sd = sdst[n * H + h];
    float eself = lrelu(ssrc[n * H + h] + sd);

    float m = eself;
    for (int j = start + lane; j < end; j += 32) {
        int s = g_adj[j];
        m = fmaxf(m, lrelu(ssrc[s * H + h] + sd));
    }
#pragma unroll
    for (int o = 16; o; o >>= 1) m = fmaxf(m, __shfl_xor_sync(0xffffffffu, m, o));

    float wself = __expf(eself - m);
    float zpart = (lane == 0) ? wself : 0.f;
    const float* selfrow = xh + (size_t)n * F + h * 64;
    float acc0 = wself * selfrow[lane];
    float acc1 = wself * selfrow[lane + 32];

    for (int j0 = start; j0 < end; j0 += 32) {
        int j = j0 + lane;
        int s = (j < end) ? g_adj[j] : n;
        float wv = 0.f;
        if (j < end) {
            wv = __expf(lrelu(ssrc[s * H + h] + sd) - m);
            zpart += wv;
        }
        int cnt = min(32, end - j0);
        for (int k = 0; k < cnt; k++) {
            float wk = __shfl_sync(0xffffffffu, wv, k);
            int   sk = __shfl_sync(0xffffffffu, s, k);
            const float* r = xh + (size_t)sk * F + h * 64;
            acc0 = fmaf(wk, r[lane], acc0);
            acc1 = fmaf(wk, r[lane + 32], acc1);
        }
    }
#pragma unroll
    for (int o = 16; o; o >>= 1) zpart += __shfl_xor_sync(0xffffffffu, zpart, o);
    float inv = 1.f / zpart;
    agg[(size_t)n * F + h * 64 + lane]      = acc0 * inv;
    agg[(size_t)n * F + h * 64 + lane + 32] = acc1 * inv;
}

// ---------------- epilogues (write split bf16 for next GEMM) ----------------
__global__ void bias_elu_split_kernel(const float* __restrict__ in, const float* __restrict__ b,
                                      __nv_bfloat16* __restrict__ hi, __nv_bfloat16* __restrict__ lo,
                                      int total, int Fmask) {
    int i = blockIdx.x * blockDim.x + threadIdx.x;
    if (i < total) {
        float v = elu1(in[i] + b[i & Fmask]);
        __nv_bfloat16 h = __float2bfloat16(v);
        hi[i] = h;
        lo[i] = __float2bfloat16(v - __bfloat162float(h));
    }
}

__global__ void mean2_bias_elu_split_kernel(const float* __restrict__ in, const float* __restrict__ b,
                                            __nv_bfloat16* __restrict__ hi, __nv_bfloat16* __restrict__ lo,
                                            int total) {
    int i = blockIdx.x * blockDim.x + threadIdx.x;
    if (i < total) {
        int n = i >> 6, d = i & 63;
        float v = 0.5f * (in[(size_t)n * 128 + d] + in[(size_t)n * 128 + 64 + d]) + b[d];
        v = elu1(v);
        __nv_bfloat16 h = __float2bfloat16(v);
        hi[i] = h;
        lo[i] = __float2bfloat16(v - __bfloat162float(h));
    }
}

__global__ void final_bias_kernel(const float* __restrict__ in, const float* __restrict__ b,
                                  float* __restrict__ out, int total) {
    int i = blockIdx.x * blockDim.x + threadIdx.x;
    if (i < total) out[i] = in[i] + b[i & 63];
}

// ---------------- host ----------------
extern "C" void kernel_launch(void* const* d_in, const int* in_sizes, int n_in,
                              void* d_out, int out_size) {
    const float* x     = (const float*)d_in[0];
    const int*   ei    = (const int*)  d_in[1];
    const float* w1    = (const float*)d_in[2];
    const float* b1    = (const float*)d_in[3];
    const float* w2    = (const float*)d_in[4];
    const float* b2    = (const float*)d_in[5];
    const float* g1w   = (const float*)d_in[6];
    const float* g1as  = (const float*)d_in[7];
    const float* g1ad  = (const float*)d_in[8];
    const float* g1b   = (const float*)d_in[9];
    const float* g2w   = (const float*)d_in[10];
    const float* g2as  = (const float*)d_in[11];
    const float* g2ad  = (const float*)d_in[12];
    const float* g2b   = (const float*)d_in[13];
    const float* g3w   = (const float*)d_in[14];
    const float* g3as  = (const float*)d_in[15];
    const float* g3ad  = (const float*)d_in[16];
    const float* g3b   = (const float*)d_in[17];

    int E = in_sizes[1] / 2;
    if (E > EMAX) E = EMAX;
    const int* srcp = ei;
    const int* dstp = ei + E;

    float *xh, *agg, *ssrc, *sdst;
    int *deg, *cur;
    __nv_bfloat16 *Phi, *Plo, *Qhi, *Qlo, *whi, *wlo;
    cudaGetSymbolAddress((void**)&xh,   g_xh);
    cudaGetSymbolAddress((void**)&agg,  g_agg);
    cudaGetSymbolAddress((void**)&ssrc, g_ssrc);
    cudaGetSymbolAddress((void**)&sdst, g_sdst);
    cudaGetSymbolAddress((void**)&deg,  g_deg);
    cudaGetSymbolAddress((void**)&cur,  g_cur);
    cudaGetSymbolAddress((void**)&Phi,  g_Phi);
    cudaGetSymbolAddress((void**)&Plo,  g_Plo);
    cudaGetSymbolAddress((void**)&Qhi,  g_Qhi);
    cudaGetSymbolAddress((void**)&Qlo,  g_Qlo);
    cudaGetSymbolAddress((void**)&whi,  g_whi);
    cudaGetSymbolAddress((void**)&wlo,  g_wlo);

    // ---- CSR build ----
    cudaMemsetAsync(deg, 0, NN * sizeof(int));
    cudaMemsetAsync(cur, 0, NN * sizeof(int));
    deg_kernel<<<(E + 255) / 256, 256>>>(dstp, E);
    scan_kernel<<<1, 1024>>>(NN);
    scatter_kernel<<<(E + 255) / 256, 256>>>(srcp, dstp, E);

    const int GY = (NN + 127) / 128;   // 391

    // ---- split x ----
    {
        int n = NN * 256;
        split_kernel<<<(n + 255) / 256, 256>>>(x, Phi, Plo, n);
    }

    // ---- semantic MLP ----
    { int n = 256 * 128; split_kernel<<<(n + 255) / 256, 256>>>(w1, whi, wlo, n); }
    tgemm_kernel<<<dim3(1, GY), 256>>>(Phi, Plo, whi, wlo, b1, nullptr, Qhi, Qlo, NN, 256, 128, 1);
    { int n = 128 * 128; split_kernel<<<(n + 255) / 256, 256>>>(w2, whi, wlo, n); }
    tgemm_kernel<<<dim3(1, GY), 256>>>(Qhi, Qlo, whi, wlo, b2, nullptr, Phi, Plo, NN, 128, 128, 1);

    // ---- GAT 1: 128 -> 4 heads x 64, concat, elu ----
    { int n = 128 * 256; split_kernel<<<(n + 255) / 256, 256>>>(g1w, whi, wlo, n); }
    tgemm_kernel<<<dim3(2, GY), 256>>>(Phi, Plo, whi, wlo, nullptr, xh, nullptr, nullptr, NN, 128, 256, 0);
    {
        int W = NN * 4;
        score_kernel<<<(W * 32 + 255) / 256, 256>>>(xh, g1as, g1ad, ssrc, sdst, 4);
        agg_kernel  <<<(W * 32 + 255) / 256, 256>>>(xh, ssrc, sdst, agg, 4);
        int tot = NN * 256;
        bias_elu_split_kernel<<<(tot + 1023) / 1024, 1024>>>(agg, g1b, Qhi, Qlo, tot, 255);
    }

    // ---- GAT 2: 256 -> 2 heads x 64, mean, elu ----
    { int n = 256 * 128; split_kernel<<<(n + 255) / 256, 256>>>(g2w, whi, wlo, n); }
    tgemm_kernel<<<dim3(1, GY), 256>>>(Qhi, Qlo, whi, wlo, nullptr, xh, nullptr, nullptr, NN, 256, 128, 0);
    {
        int W = NN * 2;
        score_kernel<<<(W * 32 + 255) / 256, 256>>>(xh, g2as, g2ad, ssrc, sdst, 2);
        agg_kernel  <<<(W * 32 + 255) / 256, 256>>>(xh, ssrc, sdst, agg, 2);
        int tot = NN * 64;
        mean2_bias_elu_split_kernel<<<(tot + 1023) / 1024, 1024>>>(agg, g2b, Phi, Plo, tot);
    }

    // ---- GAT 3: 64 -> 1 head x 64 ----
    { int n = 64 * 64; split_kernel<<<(n + 255) / 256, 256>>>(g3w, whi, wlo, n); }
    tgemm_kernel<<<dim3(1, GY), 256>>>(Phi, Plo, whi, wlo, nullptr, xh, nullptr, nullptr, NN, 64, 64, 0);
    {
        int W = NN;
        score_kernel<<<(W * 32 + 255) / 256, 256>>>(xh, g3as, g3ad, ssrc, sdst, 1);
        agg_kernel  <<<(W * 32 + 255) / 256, 256>>>(xh, ssrc, sdst, agg, 1);
        int tot = NN * 64;
        final_bias_kernel<<<(tot + 1023) / 1024, 1024>>>(agg, g3b, (float*)d_out, tot);
    }
}